// round 5
// baseline (speedup 1.0000x reference)
#include <cuda_runtime.h>
#include <math.h>

// Problem dims
#define BB 8
#define SS 512
#define HID 1024
#define NH 16
#define DD 64
#define SPAN 512

#define QKV_ELEMS (BB * SS * HID)          // 4194304
#define POS_ELEMS (NH * SS * DD)           // 524288
#define W_ELEMS   (HID * HID)              // 1048576

// Scratch (device globals; no runtime allocation allowed)
__device__ float g_Q[QKV_ELEMS];           // [b,h,s,d] tf32-rounded, pre-scaled
__device__ float g_K[QKV_ELEMS];
__device__ float g_V[QKV_ELEMS];
__device__ float g_PK[POS_ELEMS];          // [h, jj, d] tf32-rounded
__device__ float g_PQ[POS_ELEMS];          // pre-scaled
// tf32-rounded copies of inputs (feed cp.async GEMM with no cvt)
__device__ float g_qc[QKV_ELEMS];
__device__ float g_kc[QKV_ELEMS];
__device__ float g_vc[QKV_ELEMS];
__device__ float g_relc[SPAN * HID];       // rel_emb rows 512..1023
__device__ float g_Wc[5 * W_ELEMS];        // Wq,Wk,Wv,Wpk,Wpq

__device__ __forceinline__ unsigned cvt_tf32(float f) {
    unsigned r;
    asm("cvt.rna.tf32.f32 %0, %1;" : "=r"(r) : "f"(f));
    return r;
}

__device__ __forceinline__ void mma8(float* d, unsigned a0, unsigned a1,
                                     unsigned a2, unsigned a3,
                                     unsigned b0, unsigned b1) {
    asm volatile(
        "mma.sync.aligned.m16n8k8.row.col.f32.tf32.tf32.f32 "
        "{%0,%1,%2,%3}, {%4,%5,%6,%7}, {%8,%9}, {%0,%1,%2,%3};"
        : "+f"(d[0]), "+f"(d[1]), "+f"(d[2]), "+f"(d[3])
        : "r"(a0), "r"(a1), "r"(a2), "r"(a3), "r"(b0), "r"(b1));
}

__device__ __forceinline__ void cp16(unsigned dst, const void* src, bool p) {
    asm volatile("cp.async.cg.shared.global [%0], [%1], 16, %2;"
                 :: "r"(dst), "l"(src), "r"(p ? 16 : 0));
}
__device__ __forceinline__ void cp_commit() {
    asm volatile("cp.async.commit_group;");
}
template <int N>
__device__ __forceinline__ void cp_wait() {
    asm volatile("cp.async.wait_group %0;" :: "n"(N));
}

// ---------------------------------------------------------------------------
// Pre-convert: round inputs to tf32 bit patterns once.
// ---------------------------------------------------------------------------
struct CvtArgs { const float* src[9]; };

__global__ __launch_bounds__(256) void cvt_pass(CvtArgs a)
{
    const int seg = blockIdx.y;
    float* dtab[9] = { g_qc, g_kc, g_vc, g_relc,
                       g_Wc, g_Wc + W_ELEMS, g_Wc + 2 * W_ELEMS,
                       g_Wc + 3 * W_ELEMS, g_Wc + 4 * W_ELEMS };
    const int n4tab[9] = { QKV_ELEMS / 4, QKV_ELEMS / 4, QKV_ELEMS / 4,
                           (SPAN * HID) / 4, W_ELEMS / 4, W_ELEMS / 4,
                           W_ELEMS / 4, W_ELEMS / 4, W_ELEMS / 4 };
    const float4* s = (const float4*)a.src[seg];
    float4* d = (float4*)dtab[seg];
    const int n4 = n4tab[seg];
    const int stride = gridDim.x * blockDim.x;
    for (int i = blockIdx.x * blockDim.x + threadIdx.x; i < n4; i += stride) {
        float4 v = s[i];
        float4 o;
        o.x = __uint_as_float(cvt_tf32(v.x));
        o.y = __uint_as_float(cvt_tf32(v.y));
        o.z = __uint_as_float(cvt_tf32(v.z));
        o.w = __uint_as_float(cvt_tf32(v.w));
        d[i] = o;
    }
}

// ---------------------------------------------------------------------------
// tf32 GEMM with cp.async 3-stage pipeline (validated round 4).
// ---------------------------------------------------------------------------
struct GemmArgs {
    const float* bias[3];
    float oscale[3];
    int xsel[3];     // 0..3 -> g_qc/g_kc/g_vc/g_relc
    int wsel[3];     // index into g_Wc
    int mode;        // 0: QKV layout, 1: PK/PQ layout
    int dst0;        // 0..4 -> g_Q..g_PQ
};

#define ASTR 36
#define STAGE_U (2 * 128 * ASTR)
#define GEMM_SMEM (3 * STAGE_U * 4)

__global__ __launch_bounds__(256, 2) void gemm_tc(GemmArgs args)
{
    extern __shared__ unsigned gsm[];
    const int z = blockIdx.z;
    const float* Xtab[4] = { g_qc, g_kc, g_vc, g_relc };
    const float* X = Xtab[args.xsel[z]];
    const float* W = g_Wc + (size_t)args.wsel[z] * W_ELEMS;
    const float* bias = args.bias[z];
    float* Ytab[5] = { g_Q, g_K, g_V, g_PK, g_PQ };
    float* Y = Ytab[args.dst0 + z];
    const float sc = args.oscale[z];

    const int tid = threadIdx.x;
    const int wid = tid >> 5;
    const int lane = tid & 31;
    const int gr = lane >> 2;
    const int gc = lane & 3;
    const int m0 = blockIdx.y * 128;
    const int n0 = blockIdx.x * 128;
    const int warp_m = (wid & 1) * 64;
    const int warp_n = (wid >> 1) * 32;

    const unsigned sbase = (unsigned)__cvta_generic_to_shared(gsm);
    const int r0 = tid >> 3;
    const int kc = (tid & 7) * 4;

    auto issue = [&](int s, int k0) {
        const unsigned abase = sbase + (unsigned)(s * STAGE_U) * 4u;
        const unsigned bbase = abase + 128u * ASTR * 4u;
#pragma unroll
        for (int i = 0; i < 4; i++) {
            const int r = r0 + i * 32;
            cp16(abase + (unsigned)(r * ASTR + kc) * 4u,
                 X + (size_t)(m0 + r) * 1024 + k0 + kc, true);
            cp16(bbase + (unsigned)(r * ASTR + kc) * 4u,
                 W + (size_t)(n0 + r) * 1024 + k0 + kc, true);
        }
        cp_commit();
    };

    float d[4][4][4];
#pragma unroll
    for (int mt = 0; mt < 4; mt++)
#pragma unroll
        for (int nt = 0; nt < 4; nt++)
#pragma unroll
            for (int e = 0; e < 4; e++) d[mt][nt][e] = 0.f;

    issue(0, 0);
    issue(1, 32);

    for (int it = 0; it < 32; ++it) {
        if (it == 31) cp_wait<0>(); else cp_wait<1>();
        __syncthreads();
        if (it + 2 < 32) issue((it + 2) % 3, (it + 2) * 32);

        const unsigned* As = gsm + (it % 3) * STAGE_U;
        const unsigned* Bs = As + 128 * ASTR;
#pragma unroll
        for (int ks = 0; ks < 4; ks++) {
            const int kk = ks * 8;
            unsigned a[4][4], b[4][2];
#pragma unroll
            for (int mt = 0; mt < 4; mt++) {
                const int r = warp_m + mt * 16 + gr;
                a[mt][0] = As[r * ASTR + kk + gc];
                a[mt][1] = As[(r + 8) * ASTR + kk + gc];
                a[mt][2] = As[r * ASTR + kk + 4 + gc];
                a[mt][3] = As[(r + 8) * ASTR + kk + 4 + gc];
            }
#pragma unroll
            for (int nt = 0; nt < 4; nt++) {
                const int c = warp_n + nt * 8 + gr;
                b[nt][0] = Bs[c * ASTR + kk + gc];
                b[nt][1] = Bs[c * ASTR + kk + 4 + gc];
            }
#pragma unroll
            for (int mt = 0; mt < 4; mt++)
#pragma unroll
                for (int nt = 0; nt < 4; nt++)
                    mma8(d[mt][nt], a[mt][0], a[mt][1], a[mt][2], a[mt][3],
                         b[nt][0], b[nt][1]);
        }
    }

#pragma unroll
    for (int mt = 0; mt < 4; mt++) {
#pragma unroll
        for (int nt = 0; nt < 4; nt++) {
            const int n = n0 + warp_n + nt * 8 + gc * 2;
            const int h = n >> 6;
            const int dd = n & 63;
            const float b0 = bias[n], b1 = bias[n + 1];
#pragma unroll
            for (int half = 0; half < 2; half++) {
                const int m = m0 + warp_m + mt * 16 + gr + half * 8;
                size_t idx;
                if (args.mode == 0)
                    idx = ((size_t)((m >> 9) * 16 + h) * 512 + (m & 511)) * 64 + dd;
                else
                    idx = ((size_t)h * 512 + m) * 64 + dd;
                float2 o;
                o.x = __uint_as_float(cvt_tf32((d[mt][nt][half * 2 + 0] + b0) * sc));
                o.y = __uint_as_float(cvt_tf32((d[mt][nt][half * 2 + 1] + b1) * sc));
                *(float2*)&Y[idx] = o;
            }
        }
    }
}

// ---------------------------------------------------------------------------
// Tensor-core fused disentangled attention with cross-iteration pipelining:
//  - K / V-staging double-buffered via cp.async, issued one ktile ahead
//  - PK/PQ 128-row sliding window kept in a ring (slot = jj & 127);
//    only 64 new rows loaded per ktile into the just-freed slots
//  - C2P/P2C stored in shifted band layout: gather becomes
//    C2Ps[q][63-c] + P2Cs[c][q]
// ---------------------------------------------------------------------------
#define TST 68
// float offsets inside dynamic smem
#define OFF_Q    0
#define OFF_K    4352         // 2 buffers
#define OFF_VT   (OFF_K + 2 * 4352)
#define OFF_VS   (OFF_VT + 4352)   // 2 buffers
#define OFF_P    (OFF_VS + 2 * 4352)
#define OFF_PK   (OFF_P + 4352)    // 128 x 68 ring
#define OFF_PQ   (OFF_PK + 8704)
#define OFF_C2P  (OFF_PQ + 8704)
#define OFF_P2C  (OFF_C2P + 4352)
#define OFF_RM   (OFF_P2C + 4352)
#define OFF_RS   (OFF_RM + 128)
#define SMEM_ATTN ((OFF_RS + 128) * 4)     // 227,328 bytes

__global__ __launch_bounds__(256, 1) void attn_tc(float* __restrict__ out)
{
    extern __shared__ float smf[];
    unsigned* Qs   = (unsigned*)smf + OFF_Q;
    unsigned* KsB  = (unsigned*)smf + OFF_K;
    unsigned* Vts  = (unsigned*)smf + OFF_VT;
    float*    Vst  = smf + OFF_VS;
    unsigned* Ps   = (unsigned*)smf + OFF_P;
    unsigned* PKr  = (unsigned*)smf + OFF_PK;
    unsigned* PQr  = (unsigned*)smf + OFF_PQ;
    float*    C2Ps = smf + OFF_C2P;
    float*    P2Cs = smf + OFF_P2C;
    float*    redm = smf + OFF_RM;
    float*    reds = smf + OFF_RS;

    const int qt = blockIdx.x, h = blockIdx.y, b = blockIdx.z;
    const int q0 = qt * 64;
    const int tid = threadIdx.x;
    const int wid = tid >> 5, lane = tid & 31;
    const int wm = wid & 3, wn = wid >> 2;
    const int gr = lane >> 2, gc = lane & 3;
    const int rA = wm * 16;
    const int lr0 = rA + gr, lr1 = rA + gr + 8;

    const float* Qg  = g_Q + ((size_t)(b * NH + h) * SS + q0) * DD;
    const float* Kb  = g_K + (size_t)(b * NH + h) * SS * DD;
    const float* Vb  = g_V + (size_t)(b * NH + h) * SS * DD;
    const float* PKh = g_PK + (size_t)h * SS * DD;
    const float* PQh = g_PQ + (size_t)h * SS * DD;

    const unsigned sQ  = (unsigned)__cvta_generic_to_shared(Qs);
    const unsigned sK  = (unsigned)__cvta_generic_to_shared(KsB);
    const unsigned sVs = (unsigned)__cvta_generic_to_shared(Vst);
    const unsigned sPK = (unsigned)__cvta_generic_to_shared(PKr);
    const unsigned sPQ = (unsigned)__cvta_generic_to_shared(PQr);

    // ---- prologue: Q + (K, Vstage, full 128-row window) for kt=0 ----
#pragma unroll
    for (int i = 0; i < 4; i++) {
        const int id = tid + 256 * i;
        const int r = id >> 4, c4 = (id & 15) * 4;
        const unsigned so = (unsigned)(r * TST + c4) * 4u;
        cp16(sQ + so, Qg + r * 64 + c4, true);
        cp16(sK + so, Kb + r * 64 + c4, true);
        cp16(sVs + so, Vb + r * 64 + c4, true);
    }
#pragma unroll
    for (int i = 0; i < 8; i++) {
        const int id = tid + 256 * i;
        const int r = id >> 4, c4 = (id & 15) * 4;     // r in 0..127
        const int jj = q0 - 63 + r;
        const bool ok = (jj >= 0) & (jj < 512);
        const int jc = ok ? jj : 0;
        const unsigned so = (unsigned)((jj & 127) * TST + c4) * 4u;
        cp16(sPK + so, PKh + (size_t)jc * 64 + c4, ok);
        cp16(sPQ + so, PQh + (size_t)jc * 64 + c4, ok);
    }
    cp_commit();

    float O[4][4];
#pragma unroll
    for (int nt = 0; nt < 4; nt++)
#pragma unroll
        for (int e = 0; e < 4; e++) O[nt][e] = 0.f;
    float m_pr[2] = { -INFINITY, -INFINITY };
    float l_pr[2] = { 0.f, 0.f };

    for (int kt = 0; kt <= qt; kt++) {
        const int k0 = kt * 64;
        const int buf = kt & 1;

        cp_wait<0>();
        __syncthreads();

        // ---- V transpose: Vstage[buf] -> Vts ----
        {
            const float* vs = Vst + buf * 4352;
#pragma unroll
            for (int i = 0; i < 4; i++) {
                const int id = tid + 256 * i;
                const int r = id >> 4, c4 = (id & 15) * 4;
                float4 w = *(const float4*)&vs[r * TST + c4];
                Vts[(c4 + 0) * TST + r] = __float_as_uint(w.x);
                Vts[(c4 + 1) * TST + r] = __float_as_uint(w.y);
                Vts[(c4 + 2) * TST + r] = __float_as_uint(w.z);
                Vts[(c4 + 3) * TST + r] = __float_as_uint(w.w);
            }
        }

        // ---- A-phase: C2P + S (shared Q frags), then P2C ----
        const unsigned* Ksb = KsB + buf * 4352;
        const int base = q0 - k0 - 63;
        int wrow[8];
#pragma unroll
        for (int nt = 0; nt < 8; nt++)
            wrow[nt] = ((base + wn * 64 + nt * 8 + gr) & 127) * TST;

        float sacc[4][4];
#pragma unroll
        for (int nt = 0; nt < 4; nt++)
#pragma unroll
            for (int e = 0; e < 4; e++) sacc[nt][e] = 0.f;
        {
            float acc[8][4];
#pragma unroll
            for (int nt = 0; nt < 8; nt++)
#pragma unroll
                for (int e = 0; e < 4; e++) acc[nt][e] = 0.f;
#pragma unroll
            for (int ks = 0; ks < 8; ks++) {
                const int kk = ks * 8;
                unsigned a0 = Qs[lr0 * TST + kk + gc];
                unsigned a1 = Qs[lr1 * TST + kk + gc];
                unsigned a2 = Qs[lr0 * TST + kk + 4 + gc];
                unsigned a3 = Qs[lr1 * TST + kk + 4 + gc];
#pragma unroll
                for (int nt = 0; nt < 8; nt++)
                    mma8(acc[nt], a0, a1, a2, a3,
                         PKr[wrow[nt] + kk + gc], PKr[wrow[nt] + kk + 4 + gc]);
#pragma unroll
                for (int nt = 0; nt < 4; nt++) {
                    const int c = wn * 32 + nt * 8 + gr;
                    mma8(sacc[nt], a0, a1, a2, a3,
                         Ksb[c * TST + kk + gc], Ksb[c * TST + kk + 4 + gc]);
                }
            }
            // C2P shifted-band epilogue: C2Ps[q][wcol - q], keep 0..63
#pragma unroll
            for (int nt = 0; nt < 8; nt++) {
                const int wcol = wn * 64 + nt * 8 + gc * 2;
                const int j0 = wcol - lr0;
                if (j0 >= 0 && j0 < 64)         C2Ps[lr0 * TST + j0]     = acc[nt][0];
                if (j0 + 1 >= 0 && j0 + 1 < 64) C2Ps[lr0 * TST + j0 + 1] = acc[nt][1];
                const int j1 = wcol - lr1;
                if (j1 >= 0 && j1 < 64)         C2Ps[lr1 * TST + j1]     = acc[nt][2];
                if (j1 + 1 >= 0 && j1 + 1 < 64) C2Ps[lr1 * TST + j1 + 1] = acc[nt][3];
            }
#pragma unroll
            for (int nt = 0; nt < 8; nt++)
#pragma unroll
                for (int e = 0; e < 4; e++) acc[nt][e] = 0.f;
#pragma unroll
            for (int ks = 0; ks < 8; ks++) {
                const int kk = ks * 8;
                unsigned a0 = Ksb[lr0 * TST + kk + gc];
                unsigned a1 = Ksb[lr1 * TST + kk + gc];
                unsigned a2 = Ksb[lr0 * TST + kk + 4 + gc];
                unsigned a3 = Ksb[lr1 * TST + kk + 4 + gc];
#pragma unroll
                for (int nt = 0; nt < 8; nt++)
                    mma8(acc[nt], a0, a1, a2, a3,
                         PQr[wrow[nt] + kk + gc], PQr[wrow[nt] + kk + 4 + gc]);
            }
            // P2C shifted-band epilogue: P2Cs[k][wcol - 63 + k], keep 0..63
#pragma unroll
            for (int nt = 0; nt < 8; nt++) {
                const int wcol = wn * 64 + nt * 8 + gc * 2;
                const int j0 = wcol + lr0 - 63;
                if (j0 >= 0 && j0 < 64)         P2Cs[lr0 * TST + j0]     = acc[nt][0];
                if (j0 + 1 >= 0 && j0 + 1 < 64) P2Cs[lr0 * TST + j0 + 1] = acc[nt][1];
                const int j1 = wcol + lr1 - 63;
                if (j1 >= 0 && j1 < 64)         P2Cs[lr1 * TST + j1]     = acc[nt][2];
                if (j1 + 1 >= 0 && j1 + 1 < 64) P2Cs[lr1 * TST + j1 + 1] = acc[nt][3];
            }
        }
        __syncthreads();

        // ---- prefetch next ktile (overlaps softmax + PV) ----
        if (kt < qt) {
            const int k1 = k0 + 64;
            const int nb = (kt + 1) & 1;
            const unsigned sKn = sK + (unsigned)(nb * 4352) * 4u;
            const unsigned sVn = sVs + (unsigned)(nb * 4352) * 4u;
#pragma unroll
            for (int i = 0; i < 4; i++) {
                const int id = tid + 256 * i;
                const int r = id >> 4, c4 = (id & 15) * 4;
                const unsigned so = (unsigned)(r * TST + c4) * 4u;
                cp16(sKn + so, Kb + (size_t)(k1 + r) * 64 + c4, true);
                cp16(sVn + so, Vb + (size_t)(k1 + r) * 64 + c4, true);
            }
            const int nbase = base - 64;
#pragma unroll
            for (int i = 0; i < 4; i++) {
                const int id = tid + 256 * i;
                const int r = id >> 4, c4 = (id & 15) * 4;  // r 0..63
                const int jj = nbase + r;
                const bool ok = (jj >= 0) & (jj < 512);
                const int jc = ok ? jj : 0;
                const unsigned so = (unsigned)((jj & 127) * TST + c4) * 4u;
                cp16(sPK + so, PKh + (size_t)jc * 64 + c4, ok);
                cp16(sPQ + so, PQh + (size_t)jc * 64 + c4, ok);
            }
            cp_commit();
        }

        // ---- gather + online softmax ----
        const int dqk = q0 - k0;
        float rmax0 = -INFINITY, rmax1 = -INFINITY;
#pragma unroll
        for (int nt = 0; nt < 4; nt++) {
#pragma unroll
            for (int e = 0; e < 4; e++) {
                const int lr = (e & 2) ? lr1 : lr0;
                const int c = wn * 32 + nt * 8 + gc * 2 + (e & 1);
                float v = sacc[nt][e] + C2Ps[lr * TST + 63 - c] + P2Cs[c * TST + lr];
                v = (dqk + lr - c >= 0) ? v : -1e30f;
                sacc[nt][e] = v;
                if (e & 2) rmax1 = fmaxf(rmax1, v); else rmax0 = fmaxf(rmax0, v);
            }
        }
        rmax0 = fmaxf(rmax0, __shfl_xor_sync(0xffffffffu, rmax0, 1));
        rmax0 = fmaxf(rmax0, __shfl_xor_sync(0xffffffffu, rmax0, 2));
        rmax1 = fmaxf(rmax1, __shfl_xor_sync(0xffffffffu, rmax1, 1));
        rmax1 = fmaxf(rmax1, __shfl_xor_sync(0xffffffffu, rmax1, 2));
        if (gc == 0) {
            redm[lr0 * 2 + wn] = rmax0;
            redm[lr1 * 2 + wn] = rmax1;
        }
        asm volatile("bar.sync %0, 64;" :: "r"(wm + 1));   // wn-pair exchange

        const float mn0 = fmaxf(m_pr[0], fmaxf(redm[lr0 * 2], redm[lr0 * 2 + 1]));
        const float mn1 = fmaxf(m_pr[1], fmaxf(redm[lr1 * 2], redm[lr1 * 2 + 1]));
        const float fac0 = __expf(m_pr[0] - mn0);
        const float fac1 = __expf(m_pr[1] - mn1);
        float rs0 = 0.f, rs1 = 0.f;
#pragma unroll
        for (int nt = 0; nt < 4; nt++) {
#pragma unroll
            for (int e = 0; e < 4; e++) {
                const float mn = (e & 2) ? mn1 : mn0;
                const float p = __expf(sacc[nt][e] - mn);
                sacc[nt][e] = p;
                if (e & 2) rs1 += p; else rs0 += p;
            }
        }
        rs0 += __shfl_xor_sync(0xffffffffu, rs0, 1);
        rs0 += __shfl_xor_sync(0xffffffffu, rs0, 2);
        rs1 += __shfl_xor_sync(0xffffffffu, rs1, 1);
        rs1 += __shfl_xor_sync(0xffffffffu, rs1, 2);
        if (gc == 0) {
            reds[lr0 * 2 + wn] = rs0;
            reds[lr1 * 2 + wn] = rs1;
        }
#pragma unroll
        for (int nt = 0; nt < 4; nt++) {
            const int c0 = wn * 32 + nt * 8 + gc * 2;
            *(uint2*)&Ps[lr0 * TST + c0] = make_uint2(cvt_tf32(sacc[nt][0]), cvt_tf32(sacc[nt][1]));
            *(uint2*)&Ps[lr1 * TST + c0] = make_uint2(cvt_tf32(sacc[nt][2]), cvt_tf32(sacc[nt][3]));
        }
        __syncthreads();

        l_pr[0] = l_pr[0] * fac0 + reds[lr0 * 2] + reds[lr0 * 2 + 1];
        l_pr[1] = l_pr[1] * fac1 + reds[lr1 * 2] + reds[lr1 * 2 + 1];
        m_pr[0] = mn0;
        m_pr[1] = mn1;
#pragma unroll
        for (int nt = 0; nt < 4; nt++) {
            O[nt][0] *= fac0; O[nt][1] *= fac0;
            O[nt][2] *= fac1; O[nt][3] *= fac1;
        }

        // ---- O += P @ V ----
#pragma unroll
        for (int ks = 0; ks < 8; ks++) {
            const int kk = ks * 8;
            unsigned a0 = Ps[lr0 * TST + kk + gc];
            unsigned a1 = Ps[lr1 * TST + kk + gc];
            unsigned a2 = Ps[lr0 * TST + kk + 4 + gc];
            unsigned a3 = Ps[lr1 * TST + kk + 4 + gc];
#pragma unroll
            for (int nt = 0; nt < 4; nt++) {
                const int n = wn * 32 + nt * 8 + gr;
                mma8(O[nt], a0, a1, a2, a3,
                     Vts[n * TST + kk + gc], Vts[n * TST + kk + 4 + gc]);
            }
        }
    }

    // epilogue: out[b, s, h, d]
    const float inv0 = 1.f / l_pr[0];
    const float inv1 = 1.f / l_pr[1];
    const int row0 = q0 + lr0, row1 = q0 + lr1;
#pragma unroll
    for (int nt = 0; nt < 4; nt++) {
        const int c0 = wn * 32 + nt * 8 + gc * 2;
        *(float2*)&out[(((size_t)(b * SS + row0)) * NH + h) * DD + c0] =
            make_float2(O[nt][0] * inv0, O[nt][1] * inv0);
        *(float2*)&out[(((size_t)(b * SS + row1)) * NH + h) * DD + c0] =
            make_float2(O[nt][2] * inv1, O[nt][3] * inv1);
    }
}

// ---------------------------------------------------------------------------
extern "C" void kernel_launch(void* const* d_in, const int* in_sizes, int n_in,
                              void* d_out, int out_size)
{
    const float* q    = (const float*)d_in[0];
    const float* k    = (const float*)d_in[1];
    const float* v    = (const float*)d_in[2];
    // d_in[3] = attention_mask (causal tril) — enforced analytically in-kernel
    const float* Wq   = (const float*)d_in[4];
    const float* bq   = (const float*)d_in[5];
    const float* Wk   = (const float*)d_in[6];
    const float* bk   = (const float*)d_in[7];
    const float* Wv   = (const float*)d_in[8];
    const float* bv   = (const float*)d_in[9];
    const float* Wpk  = (const float*)d_in[10];
    const float* bpk  = (const float*)d_in[11];
    const float* Wpq  = (const float*)d_in[12];
    const float* bpq  = (const float*)d_in[13];
    const float* rel  = (const float*)d_in[14];
    float* out        = (float*)d_out;

    const float scale = 0.0721687836487032f;   // 1/sqrt(64*3)

    CvtArgs ca;
    ca.src[0] = q; ca.src[1] = k; ca.src[2] = v;
    ca.src[3] = rel + (size_t)SPAN * HID;      // rows 512..1023
    ca.src[4] = Wq; ca.src[5] = Wk; ca.src[6] = Wv;
    ca.src[7] = Wpk; ca.src[8] = Wpq;
    cvt_pass<<<dim3(160, 9), 256>>>(ca);

    cudaFuncSetAttribute(gemm_tc, cudaFuncAttributeMaxDynamicSharedMemorySize, GEMM_SMEM);

    GemmArgs a1;
    a1.bias[0] = bq; a1.bias[1] = bk; a1.bias[2] = bv;
    a1.oscale[0] = scale; a1.oscale[1] = 1.f; a1.oscale[2] = 1.f;
    a1.xsel[0] = 0; a1.xsel[1] = 1; a1.xsel[2] = 2;
    a1.wsel[0] = 0; a1.wsel[1] = 1; a1.wsel[2] = 2;
    a1.mode = 0; a1.dst0 = 0;
    gemm_tc<<<dim3(8, 32, 3), 256, GEMM_SMEM>>>(a1);

    GemmArgs a2;
    a2.bias[0] = bpk; a2.bias[1] = bpq; a2.bias[2] = bpq;
    a2.oscale[0] = 1.f; a2.oscale[1] = scale; a2.oscale[2] = scale;
    a2.xsel[0] = 3; a2.xsel[1] = 3; a2.xsel[2] = 3;
    a2.wsel[0] = 3; a2.wsel[1] = 4; a2.wsel[2] = 4;
    a2.mode = 1; a2.dst0 = 3;
    gemm_tc<<<dim3(8, 4, 2), 256, GEMM_SMEM>>>(a2);

    cudaFuncSetAttribute(attn_tc, cudaFuncAttributeMaxDynamicSharedMemorySize, SMEM_ATTN);
    attn_tc<<<dim3(8, NH, BB), 256, SMEM_ATTN>>>(out);
}

// round 6
// speedup vs baseline: 1.0399x; 1.0399x over previous
#include <cuda_runtime.h>
#include <math.h>

// Problem dims
#define BB 8
#define SS 512
#define HID 1024
#define NH 16
#define DD 64
#define SPAN 512

#define QKV_ELEMS (BB * SS * HID)          // 4194304
#define POS_ELEMS (NH * SS * DD)           // 524288
#define W_ELEMS   (HID * HID)              // 1048576

// Scratch (device globals; no runtime allocation allowed)
__device__ float g_Q[QKV_ELEMS];           // [b,h,s,d] tf32-rounded, pre-scaled
__device__ float g_K[QKV_ELEMS];
__device__ float g_V[QKV_ELEMS];
__device__ float g_PK[POS_ELEMS];          // [h, jj, d] tf32-rounded
__device__ float g_PQ[POS_ELEMS];          // pre-scaled
// tf32-rounded copies of inputs (feed cp.async GEMM with no cvt)
__device__ float g_qc[QKV_ELEMS];
__device__ float g_kc[QKV_ELEMS];
__device__ float g_vc[QKV_ELEMS];
__device__ float g_relc[SPAN * HID];       // rel_emb rows 512..1023
__device__ float g_Wc[5 * W_ELEMS];        // Wq,Wk,Wv,Wpk,Wpq

__device__ __forceinline__ unsigned cvt_tf32(float f) {
    unsigned r;
    asm("cvt.rna.tf32.f32 %0, %1;" : "=r"(r) : "f"(f));
    return r;
}

__device__ __forceinline__ void mma8(float* d, unsigned a0, unsigned a1,
                                     unsigned a2, unsigned a3,
                                     unsigned b0, unsigned b1) {
    asm volatile(
        "mma.sync.aligned.m16n8k8.row.col.f32.tf32.tf32.f32 "
        "{%0,%1,%2,%3}, {%4,%5,%6,%7}, {%8,%9}, {%0,%1,%2,%3};"
        : "+f"(d[0]), "+f"(d[1]), "+f"(d[2]), "+f"(d[3])
        : "r"(a0), "r"(a1), "r"(a2), "r"(a3), "r"(b0), "r"(b1));
}

__device__ __forceinline__ void cp16(unsigned dst, const void* src, bool p) {
    asm volatile("cp.async.cg.shared.global [%0], [%1], 16, %2;"
                 :: "r"(dst), "l"(src), "r"(p ? 16 : 0));
}
__device__ __forceinline__ void cp_commit() {
    asm volatile("cp.async.commit_group;");
}
template <int N>
__device__ __forceinline__ void cp_wait() {
    asm volatile("cp.async.wait_group %0;" :: "n"(N));
}

// ---------------------------------------------------------------------------
// Pre-convert: round inputs to tf32 bit patterns once.
// ---------------------------------------------------------------------------
struct CvtArgs { const float* src[9]; };

__global__ __launch_bounds__(256) void cvt_pass(CvtArgs a)
{
    const int seg = blockIdx.y;
    float* dtab[9] = { g_qc, g_kc, g_vc, g_relc,
                       g_Wc, g_Wc + W_ELEMS, g_Wc + 2 * W_ELEMS,
                       g_Wc + 3 * W_ELEMS, g_Wc + 4 * W_ELEMS };
    const int n4tab[9] = { QKV_ELEMS / 4, QKV_ELEMS / 4, QKV_ELEMS / 4,
                           (SPAN * HID) / 4, W_ELEMS / 4, W_ELEMS / 4,
                           W_ELEMS / 4, W_ELEMS / 4, W_ELEMS / 4 };
    const float4* s = (const float4*)a.src[seg];
    float4* d = (float4*)dtab[seg];
    const int n4 = n4tab[seg];
    const int stride = gridDim.x * blockDim.x;
    for (int i = blockIdx.x * blockDim.x + threadIdx.x; i < n4; i += stride) {
        float4 v = s[i];
        float4 o;
        o.x = __uint_as_float(cvt_tf32(v.x));
        o.y = __uint_as_float(cvt_tf32(v.y));
        o.z = __uint_as_float(cvt_tf32(v.z));
        o.w = __uint_as_float(cvt_tf32(v.w));
        d[i] = o;
    }
}

// ---------------------------------------------------------------------------
// tf32 GEMM with cp.async 3-stage pipeline (validated round 4).
// ---------------------------------------------------------------------------
struct GemmArgs {
    const float* bias[3];
    float oscale[3];
    int xsel[3];     // 0..3 -> g_qc/g_kc/g_vc/g_relc
    int wsel[3];     // index into g_Wc
    int mode;        // 0: QKV layout, 1: PK/PQ layout
    int dst0;        // 0..4 -> g_Q..g_PQ
};

#define ASTR 36
#define STAGE_U (2 * 128 * ASTR)
#define GEMM_SMEM (3 * STAGE_U * 4)

__global__ __launch_bounds__(256, 2) void gemm_tc(GemmArgs args)
{
    extern __shared__ unsigned gsm[];
    const int z = blockIdx.z;
    const float* Xtab[4] = { g_qc, g_kc, g_vc, g_relc };
    const float* X = Xtab[args.xsel[z]];
    const float* W = g_Wc + (size_t)args.wsel[z] * W_ELEMS;
    const float* bias = args.bias[z];
    float* Ytab[5] = { g_Q, g_K, g_V, g_PK, g_PQ };
    float* Y = Ytab[args.dst0 + z];
    const float sc = args.oscale[z];

    const int tid = threadIdx.x;
    const int wid = tid >> 5;
    const int lane = tid & 31;
    const int gr = lane >> 2;
    const int gc = lane & 3;
    const int m0 = blockIdx.y * 128;
    const int n0 = blockIdx.x * 128;
    const int warp_m = (wid & 1) * 64;
    const int warp_n = (wid >> 1) * 32;

    const unsigned sbase = (unsigned)__cvta_generic_to_shared(gsm);
    const int r0 = tid >> 3;
    const int kc = (tid & 7) * 4;

    auto issue = [&](int s, int k0) {
        const unsigned abase = sbase + (unsigned)(s * STAGE_U) * 4u;
        const unsigned bbase = abase + 128u * ASTR * 4u;
#pragma unroll
        for (int i = 0; i < 4; i++) {
            const int r = r0 + i * 32;
            cp16(abase + (unsigned)(r * ASTR + kc) * 4u,
                 X + (size_t)(m0 + r) * 1024 + k0 + kc, true);
            cp16(bbase + (unsigned)(r * ASTR + kc) * 4u,
                 W + (size_t)(n0 + r) * 1024 + k0 + kc, true);
        }
        cp_commit();
    };

    float d[4][4][4];
#pragma unroll
    for (int mt = 0; mt < 4; mt++)
#pragma unroll
        for (int nt = 0; nt < 4; nt++)
#pragma unroll
            for (int e = 0; e < 4; e++) d[mt][nt][e] = 0.f;

    issue(0, 0);
    issue(1, 32);

    for (int it = 0; it < 32; ++it) {
        if (it == 31) cp_wait<0>(); else cp_wait<1>();
        __syncthreads();
        if (it + 2 < 32) issue((it + 2) % 3, (it + 2) * 32);

        const unsigned* As = gsm + (it % 3) * STAGE_U;
        const unsigned* Bs = As + 128 * ASTR;
#pragma unroll
        for (int ks = 0; ks < 4; ks++) {
            const int kk = ks * 8;
            unsigned a[4][4], b[4][2];
#pragma unroll
            for (int mt = 0; mt < 4; mt++) {
                const int r = warp_m + mt * 16 + gr;
                a[mt][0] = As[r * ASTR + kk + gc];
                a[mt][1] = As[(r + 8) * ASTR + kk + gc];
                a[mt][2] = As[r * ASTR + kk + 4 + gc];
                a[mt][3] = As[(r + 8) * ASTR + kk + 4 + gc];
            }
#pragma unroll
            for (int nt = 0; nt < 4; nt++) {
                const int c = warp_n + nt * 8 + gr;
                b[nt][0] = Bs[c * ASTR + kk + gc];
                b[nt][1] = Bs[c * ASTR + kk + 4 + gc];
            }
#pragma unroll
            for (int mt = 0; mt < 4; mt++)
#pragma unroll
                for (int nt = 0; nt < 4; nt++)
                    mma8(d[mt][nt], a[mt][0], a[mt][1], a[mt][2], a[mt][3],
                         b[nt][0], b[nt][1]);
        }
    }

#pragma unroll
    for (int mt = 0; mt < 4; mt++) {
#pragma unroll
        for (int nt = 0; nt < 4; nt++) {
            const int n = n0 + warp_n + nt * 8 + gc * 2;
            const int h = n >> 6;
            const int dd = n & 63;
            const float b0 = bias[n], b1 = bias[n + 1];
#pragma unroll
            for (int half = 0; half < 2; half++) {
                const int m = m0 + warp_m + mt * 16 + gr + half * 8;
                size_t idx;
                if (args.mode == 0)
                    idx = ((size_t)((m >> 9) * 16 + h) * 512 + (m & 511)) * 64 + dd;
                else
                    idx = ((size_t)h * 512 + m) * 64 + dd;
                float2 o;
                o.x = __uint_as_float(cvt_tf32((d[mt][nt][half * 2 + 0] + b0) * sc));
                o.y = __uint_as_float(cvt_tf32((d[mt][nt][half * 2 + 1] + b1) * sc));
                *(float2*)&Y[idx] = o;
            }
        }
    }
}

// ---------------------------------------------------------------------------
// Tensor-core fused disentangled attention.
// Trapezoid A-phase: per 16-row warp stripe s=16*wm only the 79 window
// columns actually gathered are computed:
//   C2P needs wcol in [s, s+78]       (5 n8-tiles per wn half of 40 cols)
//   P2C needs wcol in [48-s, 126-s]   (5 n8-tiles per wn half)
// vs the previous full 128-wide rectangles (8 tiles per half).
// ---------------------------------------------------------------------------
#define TST 68
// float offsets inside dynamic smem
#define OFF_Q    0
#define OFF_K    4352         // 2 buffers
#define OFF_VT   (OFF_K + 2 * 4352)
#define OFF_VS   (OFF_VT + 4352)   // 2 buffers
#define OFF_P    (OFF_VS + 2 * 4352)
#define OFF_PK   (OFF_P + 4352)    // 128 x 68 ring
#define OFF_PQ   (OFF_PK + 8704)
#define OFF_C2P  (OFF_PQ + 8704)
#define OFF_P2C  (OFF_C2P + 4352)
#define OFF_RM   (OFF_P2C + 4352)
#define OFF_RS   (OFF_RM + 128)
#define SMEM_ATTN ((OFF_RS + 128) * 4)     // 227,328 bytes

__global__ __launch_bounds__(256, 1) void attn_tc(float* __restrict__ out)
{
    extern __shared__ float smf[];
    unsigned* Qs   = (unsigned*)smf + OFF_Q;
    unsigned* KsB  = (unsigned*)smf + OFF_K;
    unsigned* Vts  = (unsigned*)smf + OFF_VT;
    float*    Vst  = smf + OFF_VS;
    unsigned* Ps   = (unsigned*)smf + OFF_P;
    unsigned* PKr  = (unsigned*)smf + OFF_PK;
    unsigned* PQr  = (unsigned*)smf + OFF_PQ;
    float*    C2Ps = smf + OFF_C2P;
    float*    P2Cs = smf + OFF_P2C;
    float*    redm = smf + OFF_RM;
    float*    reds = smf + OFF_RS;

    const int qt = blockIdx.x, h = blockIdx.y, b = blockIdx.z;
    const int q0 = qt * 64;
    const int tid = threadIdx.x;
    const int wid = tid >> 5, lane = tid & 31;
    const int wm = wid & 3, wn = wid >> 2;
    const int gr = lane >> 2, gc = lane & 3;
    const int sA = wm * 16;                    // warp's 16-row stripe
    const int lr0 = sA + gr, lr1 = sA + gr + 8;

    const float* Qg  = g_Q + ((size_t)(b * NH + h) * SS + q0) * DD;
    const float* Kb  = g_K + (size_t)(b * NH + h) * SS * DD;
    const float* Vb  = g_V + (size_t)(b * NH + h) * SS * DD;
    const float* PKh = g_PK + (size_t)h * SS * DD;
    const float* PQh = g_PQ + (size_t)h * SS * DD;

    const unsigned sQ  = (unsigned)__cvta_generic_to_shared(Qs);
    const unsigned sK  = (unsigned)__cvta_generic_to_shared(KsB);
    const unsigned sVs = (unsigned)__cvta_generic_to_shared(Vst);
    const unsigned sPK = (unsigned)__cvta_generic_to_shared(PKr);
    const unsigned sPQ = (unsigned)__cvta_generic_to_shared(PQr);

    // ---- prologue: Q + (K, Vstage, full 128-row window) for kt=0 ----
#pragma unroll
    for (int i = 0; i < 4; i++) {
        const int id = tid + 256 * i;
        const int r = id >> 4, c4 = (id & 15) * 4;
        const unsigned so = (unsigned)(r * TST + c4) * 4u;
        cp16(sQ + so, Qg + r * 64 + c4, true);
        cp16(sK + so, Kb + r * 64 + c4, true);
        cp16(sVs + so, Vb + r * 64 + c4, true);
    }
#pragma unroll
    for (int i = 0; i < 8; i++) {
        const int id = tid + 256 * i;
        const int r = id >> 4, c4 = (id & 15) * 4;     // r in 0..127
        const int jj = q0 - 63 + r;
        const bool ok = (jj >= 0) & (jj < 512);
        const int jc = ok ? jj : 0;
        const unsigned so = (unsigned)((jj & 127) * TST + c4) * 4u;
        cp16(sPK + so, PKh + (size_t)jc * 64 + c4, ok);
        cp16(sPQ + so, PQh + (size_t)jc * 64 + c4, ok);
    }
    cp_commit();

    float O[4][4];
#pragma unroll
    for (int nt = 0; nt < 4; nt++)
#pragma unroll
        for (int e = 0; e < 4; e++) O[nt][e] = 0.f;
    float m_pr[2] = { -INFINITY, -INFINITY };
    float l_pr[2] = { 0.f, 0.f };

    for (int kt = 0; kt <= qt; kt++) {
        const int k0 = kt * 64;
        const int buf = kt & 1;

        cp_wait<0>();
        __syncthreads();

        // ---- V transpose: Vstage[buf] -> Vts ----
        {
            const float* vs = Vst + buf * 4352;
#pragma unroll
            for (int i = 0; i < 4; i++) {
                const int id = tid + 256 * i;
                const int r = id >> 4, c4 = (id & 15) * 4;
                float4 w = *(const float4*)&vs[r * TST + c4];
                Vts[(c4 + 0) * TST + r] = __float_as_uint(w.x);
                Vts[(c4 + 1) * TST + r] = __float_as_uint(w.y);
                Vts[(c4 + 2) * TST + r] = __float_as_uint(w.z);
                Vts[(c4 + 3) * TST + r] = __float_as_uint(w.w);
            }
        }

        // ---- A-phase (trapezoid): C2P + S (shared Q frags), then P2C ----
        const unsigned* Ksb = KsB + buf * 4352;
        const int base = q0 - k0 - 63;

        // C2P tiles: wcol = sA + wn*40 + nt*8 (+gr), nt = 0..4
        const int cbase = sA + wn * 40;
        int wrC[5];
#pragma unroll
        for (int nt = 0; nt < 5; nt++)
            wrC[nt] = ((base + cbase + nt * 8 + gr) & 127) * TST;
        // P2C tiles: wcol = (48 - sA) + wn*40 + nt*8 (+gr)
        const int pbase = 48 - sA + wn * 40;
        int wrP[5];
#pragma unroll
        for (int nt = 0; nt < 5; nt++)
            wrP[nt] = ((base + pbase + nt * 8 + gr) & 127) * TST;

        float sacc[4][4];
#pragma unroll
        for (int nt = 0; nt < 4; nt++)
#pragma unroll
            for (int e = 0; e < 4; e++) sacc[nt][e] = 0.f;
        {
            float acc[5][4];
#pragma unroll
            for (int nt = 0; nt < 5; nt++)
#pragma unroll
                for (int e = 0; e < 4; e++) acc[nt][e] = 0.f;
#pragma unroll
            for (int ks = 0; ks < 8; ks++) {
                const int kk = ks * 8;
                unsigned a0 = Qs[lr0 * TST + kk + gc];
                unsigned a1 = Qs[lr1 * TST + kk + gc];
                unsigned a2 = Qs[lr0 * TST + kk + 4 + gc];
                unsigned a3 = Qs[lr1 * TST + kk + 4 + gc];
#pragma unroll
                for (int nt = 0; nt < 5; nt++)
                    mma8(acc[nt], a0, a1, a2, a3,
                         PKr[wrC[nt] + kk + gc], PKr[wrC[nt] + kk + 4 + gc]);
#pragma unroll
                for (int nt = 0; nt < 4; nt++) {
                    const int c = wn * 32 + nt * 8 + gr;
                    mma8(sacc[nt], a0, a1, a2, a3,
                         Ksb[c * TST + kk + gc], Ksb[c * TST + kk + 4 + gc]);
                }
            }
            // C2P band epilogue: C2Ps[q][wcol - q], keep j in [0,64)
#pragma unroll
            for (int nt = 0; nt < 5; nt++) {
                const int wcol = cbase + nt * 8 + gc * 2;
                const int j0 = wcol - lr0;
                if (j0 >= 0 && j0 < 64)         C2Ps[lr0 * TST + j0]     = acc[nt][0];
                if (j0 + 1 >= 0 && j0 + 1 < 64) C2Ps[lr0 * TST + j0 + 1] = acc[nt][1];
                const int j1 = wcol - lr1;
                if (j1 >= 0 && j1 < 64)         P2Cs == P2Cs ? (C2Ps[lr1 * TST + j1] = acc[nt][2]) : 0.f;
                if (j1 + 1 >= 0 && j1 + 1 < 64) C2Ps[lr1 * TST + j1 + 1] = acc[nt][3];
            }
            // P2C: K-stripe rows x PQ window tiles
#pragma unroll
            for (int nt = 0; nt < 5; nt++)
#pragma unroll
                for (int e = 0; e < 4; e++) acc[nt][e] = 0.f;
#pragma unroll
            for (int ks = 0; ks < 8; ks++) {
                const int kk = ks * 8;
                unsigned a0 = Ksb[lr0 * TST + kk + gc];
                unsigned a1 = Ksb[lr1 * TST + kk + gc];
                unsigned a2 = Ksb[lr0 * TST + kk + 4 + gc];
                unsigned a3 = Ksb[lr1 * TST + kk + 4 + gc];
#pragma unroll
                for (int nt = 0; nt < 5; nt++)
                    mma8(acc[nt], a0, a1, a2, a3,
                         PQr[wrP[nt] + kk + gc], PQr[wrP[nt] + kk + 4 + gc]);
            }
            // P2C band epilogue: P2Cs[k][wcol - 63 + k], keep j in [0,64)
#pragma unroll
            for (int nt = 0; nt < 5; nt++) {
                const int wcol = pbase + nt * 8 + gc * 2;
                const int j0 = wcol + lr0 - 63;
                if (j0 >= 0 && j0 < 64)         P2Cs[lr0 * TST + j0]     = acc[nt][0];
                if (j0 + 1 >= 0 && j0 + 1 < 64) P2Cs[lr0 * TST + j0 + 1] = acc[nt][1];
                const int j1 = wcol + lr1 - 63;
                if (j1 >= 0 && j1 < 64)         P2Cs[lr1 * TST + j1]     = acc[nt][2];
                if (j1 + 1 >= 0 && j1 + 1 < 64) P2Cs[lr1 * TST + j1 + 1] = acc[nt][3];
            }
        }
        __syncthreads();

        // ---- prefetch next ktile (overlaps softmax + PV) ----
        if (kt < qt) {
            const int k1 = k0 + 64;
            const int nb = (kt + 1) & 1;
            const unsigned sKn = sK + (unsigned)(nb * 4352) * 4u;
            const unsigned sVn = sVs + (unsigned)(nb * 4352) * 4u;
#pragma unroll
            for (int i = 0; i < 4; i++) {
                const int id = tid + 256 * i;
                const int r = id >> 4, c4 = (id & 15) * 4;
                const unsigned so = (unsigned)(r * TST + c4) * 4u;
                cp16(sKn + so, Kb + (size_t)(k1 + r) * 64 + c4, true);
                cp16(sVn + so, Vb + (size_t)(k1 + r) * 64 + c4, true);
            }
            const int nbase = base - 64;
#pragma unroll
            for (int i = 0; i < 4; i++) {
                const int id = tid + 256 * i;
                const int r = id >> 4, c4 = (id & 15) * 4;  // r 0..63
                const int jj = nbase + r;
                const bool ok = (jj >= 0) & (jj < 512);
                const int jc = ok ? jj : 0;
                const unsigned so = (unsigned)((jj & 127) * TST + c4) * 4u;
                cp16(sPK + so, PKh + (size_t)jc * 64 + c4, ok);
                cp16(sPQ + so, PQh + (size_t)jc * 64 + c4, ok);
            }
            cp_commit();
        }

        // ---- gather + online softmax ----
        const int dqk = q0 - k0;
        float rmax0 = -INFINITY, rmax1 = -INFINITY;
#pragma unroll
        for (int nt = 0; nt < 4; nt++) {
#pragma unroll
            for (int e = 0; e < 4; e++) {
                const int lr = (e & 2) ? lr1 : lr0;
                const int c = wn * 32 + nt * 8 + gc * 2 + (e & 1);
                float v = sacc[nt][e] + C2Ps[lr * TST + 63 - c] + P2Cs[c * TST + lr];
                v = (dqk + lr - c >= 0) ? v : -1e30f;
                sacc[nt][e] = v;
                if (e & 2) rmax1 = fmaxf(rmax1, v); else rmax0 = fmaxf(rmax0, v);
            }
        }
        rmax0 = fmaxf(rmax0, __shfl_xor_sync(0xffffffffu, rmax0, 1));
        rmax0 = fmaxf(rmax0, __shfl_xor_sync(0xffffffffu, rmax0, 2));
        rmax1 = fmaxf(rmax1, __shfl_xor_sync(0xffffffffu, rmax1, 1));
        rmax1 = fmaxf(rmax1, __shfl_xor_sync(0xffffffffu, rmax1, 2));
        if (gc == 0) {
            redm[lr0 * 2 + wn] = rmax0;
            redm[lr1 * 2 + wn] = rmax1;
        }
        asm volatile("bar.sync %0, 64;" :: "r"(wm + 1));   // wn-pair exchange

        const float mn0 = fmaxf(m_pr[0], fmaxf(redm[lr0 * 2], redm[lr0 * 2 + 1]));
        const float mn1 = fmaxf(m_pr[1], fmaxf(redm[lr1 * 2], redm[lr1 * 2 + 1]));
        const float fac0 = __expf(m_pr[0] - mn0);
        const float fac1 = __expf(m_pr[1] - mn1);
        float rs0 = 0.f, rs1 = 0.f;
#pragma unroll
        for (int nt = 0; nt < 4; nt++) {
#pragma unroll
            for (int e = 0; e < 4; e++) {
                const float mn = (e & 2) ? mn1 : mn0;
                const float p = __expf(sacc[nt][e] - mn);
                sacc[nt][e] = p;
                if (e & 2) rs1 += p; else rs0 += p;
            }
        }
        rs0 += __shfl_xor_sync(0xffffffffu, rs0, 1);
        rs0 += __shfl_xor_sync(0xffffffffu, rs0, 2);
        rs1 += __shfl_xor_sync(0xffffffffu, rs1, 1);
        rs1 += __shfl_xor_sync(0xffffffffu, rs1, 2);
        if (gc == 0) {
            reds[lr0 * 2 + wn] = rs0;
            reds[lr1 * 2 + wn] = rs1;
        }
#pragma unroll
        for (int nt = 0; nt < 4; nt++) {
            const int c0 = wn * 32 + nt * 8 + gc * 2;
            *(uint2*)&Ps[lr0 * TST + c0] = make_uint2(cvt_tf32(sacc[nt][0]), cvt_tf32(sacc[nt][1]));
            *(uint2*)&Ps[lr1 * TST + c0] = make_uint2(cvt_tf32(sacc[nt][2]), cvt_tf32(sacc[nt][3]));
        }
        __syncthreads();

        l_pr[0] = l_pr[0] * fac0 + reds[lr0 * 2] + reds[lr0 * 2 + 1];
        l_pr[1] = l_pr[1] * fac1 + reds[lr1 * 2] + reds[lr1 * 2 + 1];
        m_pr[0] = mn0;
        m_pr[1] = mn1;
#pragma unroll
        for (int nt = 0; nt < 4; nt++) {
            O[nt][0] *= fac0; O[nt][1] *= fac0;
            O[nt][2] *= fac1; O[nt][3] *= fac1;
        }

        // ---- O += P @ V ----
#pragma unroll
        for (int ks = 0; ks < 8; ks++) {
            const int kk = ks * 8;
            unsigned a0 = Ps[lr0 * TST + kk + gc];
            unsigned a1 = Ps[lr1 * TST + kk + gc];
            unsigned a2 = Ps[lr0 * TST + kk + 4 + gc];
            unsigned a3 = Ps[lr1 * TST + kk + 4 + gc];
#pragma unroll
            for (int nt = 0; nt < 4; nt++) {
                const int n = wn * 32 + nt * 8 + gr;
                mma8(O[nt], a0, a1, a2, a3,
                     Vts[n * TST + kk + gc], Vts[n * TST + kk + 4 + gc]);
            }
        }
    }

    // epilogue: out[b, s, h, d]
    const float inv0 = 1.f / l_pr[0];
    const float inv1 = 1.f / l_pr[1];
    const int row0 = q0 + lr0, row1 = q0 + lr1;
#pragma unroll
    for (int nt = 0; nt < 4; nt++) {
        const int c0 = wn * 32 + nt * 8 + gc * 2;
        *(float2*)&out[(((size_t)(b * SS + row0)) * NH + h) * DD + c0] =
            make_float2(O[nt][0] * inv0, O[nt][1] * inv0);
        *(float2*)&out[(((size_t)(b * SS + row1)) * NH + h) * DD + c0] =
            make_float2(O[nt][2] * inv1, O[nt][3] * inv1);
    }
}

// ---------------------------------------------------------------------------
extern "C" void kernel_launch(void* const* d_in, const int* in_sizes, int n_in,
                              void* d_out, int out_size)
{
    const float* q    = (const float*)d_in[0];
    const float* k    = (const float*)d_in[1];
    const float* v    = (const float*)d_in[2];
    // d_in[3] = attention_mask (causal tril) — enforced analytically in-kernel
    const float* Wq   = (const float*)d_in[4];
    const float* bq   = (const float*)d_in[5];
    const float* Wk   = (const float*)d_in[6];
    const float* bk   = (const float*)d_in[7];
    const float* Wv   = (const float*)d_in[8];
    const float* bv   = (const float*)d_in[9];
    const float* Wpk  = (const float*)d_in[10];
    const float* bpk  = (const float*)d_in[11];
    const float* Wpq  = (const float*)d_in[12];
    const float* bpq  = (const float*)d_in[13];
    const float* rel  = (const float*)d_in[14];
    float* out        = (float*)d_out;

    const float scale = 0.0721687836487032f;   // 1/sqrt(64*3)

    CvtArgs ca;
    ca.src[0] = q; ca.src[1] = k; ca.src[2] = v;
    ca.src[3] = rel + (size_t)SPAN * HID;      // rows 512..1023
    ca.src[4] = Wq; ca.src[5] = Wk; ca.src[6] = Wv;
    ca.src[7] = Wpk; ca.src[8] = Wpq;
    cvt_pass<<<dim3(160, 9), 256>>>(ca);

    cudaFuncSetAttribute(gemm_tc, cudaFuncAttributeMaxDynamicSharedMemorySize, GEMM_SMEM);

    GemmArgs a1;
    a1.bias[0] = bq; a1.bias[1] = bk; a1.bias[2] = bv;
    a1.oscale[0] = scale; a1.oscale[1] = 1.f; a1.oscale[2] = 1.f;
    a1.xsel[0] = 0; a1.xsel[1] = 1; a1.xsel[2] = 2;
    a1.wsel[0] = 0; a1.wsel[1] = 1; a1.wsel[2] = 2;
    a1.mode = 0; a1.dst0 = 0;
    gemm_tc<<<dim3(8, 32, 3), 256, GEMM_SMEM>>>(a1);

    GemmArgs a2;
    a2.bias[0] = bpk; a2.bias[1] = bpq; a2.bias[2] = bpq;
    a2.oscale[0] = 1.f; a2.oscale[1] = scale; a2.oscale[2] = scale;
    a2.xsel[0] = 3; a2.xsel[1] = 3; a2.xsel[2] = 3;
    a2.wsel[0] = 3; a2.wsel[1] = 4; a2.wsel[2] = 4;
    a2.mode = 1; a2.dst0 = 3;
    gemm_tc<<<dim3(8, 4, 2), 256, GEMM_SMEM>>>(a2);

    cudaFuncSetAttribute(attn_tc, cudaFuncAttributeMaxDynamicSharedMemorySize, SMEM_ATTN);
    attn_tc<<<dim3(8, NH, BB), 256, SMEM_ATTN>>>(out);
}